// round 14
// baseline (speedup 1.0000x reference)
#include <cuda_runtime.h>
#include <cstdint>

#define BB 16384
#define TT 2048

// Scratch: x transposed to [T, B]; padded by one timestep so the prefetch of
// t+1 never branches (last prefetched value is read but never used).
__device__ float g_xT[(size_t)BB * (size_t)(TT + 1)];

typedef unsigned long long ull;

__device__ __forceinline__ ull pk2(float a, float b) {
    ull r; asm("mov.b64 %0, {%1, %2};" : "=l"(r) : "f"(a), "f"(b)); return r;
}
__device__ __forceinline__ void upk2(ull v, float& a, float& b) {
    asm("mov.b64 {%0, %1}, %2;" : "=f"(a), "=f"(b) : "l"(v));
}
__device__ __forceinline__ ull ffma2(ull a, ull b, ull c) {
    ull d; asm("fma.rn.f32x2 %0, %1, %2, %3;" : "=l"(d) : "l"(a), "l"(b), "l"(c)); return d;
}
__device__ __forceinline__ ull fsub2(ull a, ull b) {
    ull d; asm("sub.rn.f32x2 %0, %1, %2;" : "=l"(d) : "l"(a), "l"(b)); return d;
}
// MUFU.TANH — single-instruction tanh (sm_75+)
__device__ __forceinline__ float tanh_mufu(float x) {
    float y; asm("tanh.approx.f32 %0, %1;" : "=f"(y) : "f"(x)); return y;
}
__device__ __forceinline__ float hadd2(ull v) {
    float a, b; upk2(v, a, b); return a + b;
}

// ---------------------------------------------------------------------------
// Kernel 1: transpose x [B, T] -> g_xT [T, B]
// ---------------------------------------------------------------------------
__global__ void transpose_kernel(const float* __restrict__ x) {
    __shared__ float tile[32][33];
    int t0 = blockIdx.x * 32;
    int b0 = blockIdx.y * 32;
    int tx = threadIdx.x, ty = threadIdx.y;
#pragma unroll
    for (int i = 0; i < 4; i++) {
        tile[ty + i * 8][tx] = x[(size_t)(b0 + ty + i * 8) * TT + (t0 + tx)];
    }
    __syncthreads();
#pragma unroll
    for (int i = 0; i < 4; i++) {
        g_xT[(size_t)(t0 + ty + i * 8) * BB + (b0 + tx)] = tile[tx][ty + i * 8];
    }
}

// ---------------------------------------------------------------------------
// Kernel 2: GRU scan — software-pipelined 2-pair schedule.
//   Each thread: 2 batch pairs (4 elems), half-step out of phase:
//     dot(P0) ; tail(P1)+write ; syncwarp ; dot(P1) ; tail(P0)+write ; syncwarp
//   -> the MUFU-heavy tail of one pair interleaves with the FMA-heavy dot of
//      the other INSIDE each warp: fma/MUFU/LSU pipes overlap without relying
//      on cross-warp de-phasing (measured to fail in rounds 4-13).
//   - k-packed weights (24 ull = 48 regs, spill-free).
//   - Packed f32x2 tails (round 11).
//   - SINGLE h buffer per pair: the two syncwarps double as the WAR
//     separators (reads of step-t h always complete before step-t+1 writes).
//   - SMEM layout: group region 80 floats; slots e0@0,e1@20,e2@40,e3@60
//     (bank offsets 0/20/8/28 -> conflict-free writes, broadcast reads).
//   - 1024 blocks x 64 thr, __launch_bounds__(64,9): cap 113 regs, one wave.
//   - r/z weights+biases pre-scaled by 0.5 (sigmoid via tanh identity).
// ---------------------------------------------------------------------------

#define GREG 80
#define E1OFF 20
#define E2OFF 40
#define E3OFF 60

// 6-chain k-packed dot for one pair; bias-initialized accumulators.
__device__ __forceinline__ void dot_pair(
    const float* __restrict__ eA, const float* __restrict__ eB,
    const ull wr2[8], const ull wz2[8], const ull wn2[8],
    ull bR2, ull bZ2, ull bN2,
    ull& aRA, ull& aZA, ull& aNA, ull& aRB, ull& aZB, ull& aNB)
{
    ulonglong2 vA = *(const ulonglong2*)(eA);
    ulonglong2 vB = *(const ulonglong2*)(eB);
    aRA = ffma2(wr2[0], vA.x, bR2);  aRB = ffma2(wr2[0], vB.x, bR2);
    aZA = ffma2(wz2[0], vA.x, bZ2);  aZB = ffma2(wz2[0], vB.x, bZ2);
    aNA = ffma2(wn2[0], vA.x, bN2);  aNB = ffma2(wn2[0], vB.x, bN2);
    aRA = ffma2(wr2[1], vA.y, aRA);  aRB = ffma2(wr2[1], vB.y, aRB);
    aZA = ffma2(wz2[1], vA.y, aZA);  aZB = ffma2(wz2[1], vB.y, aZB);
    aNA = ffma2(wn2[1], vA.y, aNA);  aNB = ffma2(wn2[1], vB.y, aNB);
#pragma unroll
    for (int c = 1; c < 4; c++) {
        ulonglong2 uA = *(const ulonglong2*)(eA + 4 * c);
        ulonglong2 uB = *(const ulonglong2*)(eB + 4 * c);
        aRA = ffma2(wr2[2 * c], uA.x, aRA);      aRB = ffma2(wr2[2 * c], uB.x, aRB);
        aZA = ffma2(wz2[2 * c], uA.x, aZA);      aZB = ffma2(wz2[2 * c], uB.x, aZB);
        aNA = ffma2(wn2[2 * c], uA.x, aNA);      aNB = ffma2(wn2[2 * c], uB.x, aNB);
        aRA = ffma2(wr2[2 * c + 1], uA.y, aRA);  aRB = ffma2(wr2[2 * c + 1], uB.y, aRB);
        aZA = ffma2(wz2[2 * c + 1], uA.y, aZA);  aZB = ffma2(wz2[2 * c + 1], uB.y, aZB);
        aNA = ffma2(wn2[2 * c + 1], uA.y, aNA);  aNB = ffma2(wn2[2 * c + 1], uB.y, aNB);
    }
}

// Packed tail: accumulators -> new packed h (hA,hB).
__device__ __forceinline__ ull tail_pair(
    ull x2,
    ull aRA, ull aZA, ull aNA, ull aRB, ull aZB, ull aNB,
    ull wirp, ull wizp, ull winp, ull binp2, ull halfp, ull h)
{
    ull sR = pk2(hadd2(aRA), hadd2(aRB));
    ull sZ = pk2(hadd2(aZA), hadd2(aZB));
    ull gN = pk2(hadd2(aNA), hadd2(aNB));
    sR = ffma2(x2, wirp, sR);
    sZ = ffma2(x2, wizp, sZ);
    ull gI = ffma2(x2, winp, binp2);
    float lo, hi;
    upk2(sR, lo, hi);
    ull rr = ffma2(halfp, pk2(tanh_mufu(lo), tanh_mufu(hi)), halfp);
    upk2(sZ, lo, hi);
    ull zz = ffma2(halfp, pk2(tanh_mufu(lo), tanh_mufu(hi)), halfp);
    ull npre = ffma2(rr, gN, gI);
    upk2(npre, lo, hi);
    ull nn = pk2(tanh_mufu(lo), tanh_mufu(hi));
    return ffma2(zz, fsub2(h, nn), nn);     // h' = n + z*(h - n)
}

__global__ __launch_bounds__(64, 9)
void gru_kernel(const float* __restrict__ w_ih, const float* __restrict__ w_hh,
                const float* __restrict__ b_ih, const float* __restrict__ b_hh,
                const float* __restrict__ w_fc, const float* __restrict__ b_fc,
                float* __restrict__ out)
{
    __shared__ float hbuf[4 * GREG];

    int tid = threadIdx.x;
    int j   = tid & 15;                       // owned hidden index
    int grp = tid >> 4;                       // group within block (0..3)
    int gid = (blockIdx.x * 64 + tid) >> 4;   // global group; elems 4gid..4gid+3

    // --- k-packed register weights: 24 ull = 48 regs ---
    ull wr2[8], wz2[8], wn2[8];
#pragma unroll
    for (int m = 0; m < 8; m++) {
        wr2[m] = pk2(0.5f * __ldg(&w_hh[j * 16 + 2 * m]),
                     0.5f * __ldg(&w_hh[j * 16 + 2 * m + 1]));
        wz2[m] = pk2(0.5f * __ldg(&w_hh[(16 + j) * 16 + 2 * m]),
                     0.5f * __ldg(&w_hh[(16 + j) * 16 + 2 * m + 1]));
        wn2[m] = pk2(__ldg(&w_hh[(32 + j) * 16 + 2 * m]),
                     __ldg(&w_hh[(32 + j) * 16 + 2 * m + 1]));
    }

    // --- tail constants ---
    float wirf = 0.5f * __ldg(&w_ih[j]);
    float wizf = 0.5f * __ldg(&w_ih[16 + j]);
    float winf = __ldg(&w_ih[32 + j]);
    float bsrf = 0.5f * (__ldg(&b_ih[j]) + __ldg(&b_hh[j]));
    float bszf = 0.5f * (__ldg(&b_ih[16 + j]) + __ldg(&b_hh[16 + j]));
    float binf = __ldg(&b_ih[32 + j]);
    float bhnf = __ldg(&b_hh[32 + j]);
    ull bR2 = pk2(bsrf, 0.0f);
    ull bZ2 = pk2(bszf, 0.0f);
    ull bN2 = pk2(bhnf, 0.0f);
    ull wirp  = pk2(wirf, wirf);
    ull wizp  = pk2(wizf, wizf);
    ull winp  = pk2(winf, winf);
    ull binp2 = pk2(binf, binf);
    ull halfp = pk2(0.5f, 0.5f);

    float* bp = &hbuf[grp * GREG];

    ull h01 = 0ull, h23 = 0ull;
    bp[j]         = 0.0f;
    bp[j + E1OFF] = 0.0f;
    bp[j + E2OFF] = 0.0f;
    bp[j + E3OFF] = 0.0f;
    __syncwarp();

    const float4* xp = ((const float4*)g_xT) + gid;
    float4 xv = __ldg(xp);
    xp += (BB / 4);

    // P1 carried accumulators: prologue "dot" of h_0 = 0 is just the biases.
    ull aR2 = bR2, aZ2 = bZ2, aN2 = bN2;
    ull aR3 = bR2, aZ3 = bZ2, aN3 = bN2;

    for (int t = 0; t < TT; t++) {
        ull x01 = pk2(xv.x, xv.y);
        ull x23 = pk2(xv.z, xv.w);
        float4 xnext = __ldg(xp);      // padded array: always valid
        xp += (BB / 4);

        // (1) dot P0  (reads e0/e1 written before last sync)
        ull aR0, aZ0, aN0, aR1, aZ1, aN1;
        dot_pair(bp, bp + E1OFF, wr2, wz2, wn2, bR2, bZ2, bN2,
                 aR0, aZ0, aN0, aR1, aZ1, aN1);

        // (2) tail P1 (carried accums) -> h_{t+1}(P1); write e2/e3
        h23 = tail_pair(x23, aR2, aZ2, aN2, aR3, aZ3, aN3,
                        wirp, wizp, winp, binp2, halfp, h23);
        {
            float h2, h3;
            upk2(h23, h2, h3);
            bp[j + E2OFF] = h2;
            bp[j + E3OFF] = h3;
        }
        // (3) separates P1 writes from P1 reads AND P0 reads from P0 writes
        __syncwarp();

        // (4) dot P1 for the next step (last iteration's result is unused)
        dot_pair(bp + E2OFF, bp + E3OFF, wr2, wz2, wn2, bR2, bZ2, bN2,
                 aR2, aZ2, aN2, aR3, aZ3, aN3);

        // (5) tail P0 -> h_{t+1}(P0); write e0/e1
        h01 = tail_pair(x01, aR0, aZ0, aN0, aR1, aZ1, aN1,
                        wirp, wizp, winp, binp2, halfp, h01);
        {
            float h0, h1;
            upk2(h01, h0, h1);
            bp[j]         = h0;
            bp[j + E1OFF] = h1;
        }
        // (6) separates P0 writes from next-iter P0 reads, P1 reads from writes
        __syncwarp();

        xv = xnext;
    }

    // FC epilogue: out[b] = sum_j h[b][j] * w_fc[j] + b_fc
    float wf = __ldg(&w_fc[j]);
    float hv0, hv1, hv2, hv3;
    upk2(h01, hv0, hv1);
    upk2(h23, hv2, hv3);
    float s0 = hv0 * wf, s1 = hv1 * wf, s2 = hv2 * wf, s3 = hv3 * wf;
#pragma unroll
    for (int d = 1; d < 16; d <<= 1) {
        s0 += __shfl_xor_sync(0xffffffffu, s0, d);
        s1 += __shfl_xor_sync(0xffffffffu, s1, d);
        s2 += __shfl_xor_sync(0xffffffffu, s2, d);
        s3 += __shfl_xor_sync(0xffffffffu, s3, d);
    }
    if (j == 0) {
        float bf = __ldg(b_fc);
        float4 o;
        o.x = s0 + bf; o.y = s1 + bf; o.z = s2 + bf; o.w = s3 + bf;
        *(float4*)(out + 4 * gid) = o;
    }
}

// ---------------------------------------------------------------------------
extern "C" void kernel_launch(void* const* d_in, const int* in_sizes, int n_in,
                              void* d_out, int out_size)
{
    const float* x    = (const float*)d_in[0];
    const float* w_ih = (const float*)d_in[1];
    const float* w_hh = (const float*)d_in[2];
    const float* b_ih = (const float*)d_in[3];
    const float* b_hh = (const float*)d_in[4];
    const float* w_fc = (const float*)d_in[5];
    const float* b_fc = (const float*)d_in[6];
    float* out = (float*)d_out;

    dim3 tb(32, 8);
    dim3 tg(TT / 32, BB / 32);
    transpose_kernel<<<tg, tb>>>(x);

    // 16384 elems / 4 per 16-lane group * 16 lanes = 65536 threads
    // = 1024 blocks x 64 threads; (64,9) -> 1332 slots -> ONE WAVE.
    gru_kernel<<<1024, 64>>>(w_ih, w_hh, b_ih, b_hh, w_fc, b_fc, out);
}

// round 16
// speedup vs baseline: 1.0908x; 1.0908x over previous
#include <cuda_runtime.h>
#include <cstdint>

#define BB 16384
#define TT 2048

// Scratch: x transposed to [T, B]; padded by one timestep so the prefetch of
// t+1 never branches (last prefetched value is read but never used).
__device__ float g_xT[(size_t)BB * (size_t)(TT + 1)];

typedef unsigned long long ull;

__device__ __forceinline__ ull pk2(float a, float b) {
    ull r; asm("mov.b64 %0, {%1, %2};" : "=l"(r) : "f"(a), "f"(b)); return r;
}
__device__ __forceinline__ void upk2(ull v, float& a, float& b) {
    asm("mov.b64 {%0, %1}, %2;" : "=f"(a), "=f"(b) : "l"(v));
}
__device__ __forceinline__ ull ffma2(ull a, ull b, ull c) {
    ull d; asm("fma.rn.f32x2 %0, %1, %2, %3;" : "=l"(d) : "l"(a), "l"(b), "l"(c)); return d;
}
// MUFU.TANH — single-instruction tanh (sm_75+)
__device__ __forceinline__ float tanh_mufu(float x) {
    float y; asm("tanh.approx.f32 %0, %1;" : "=f"(y) : "f"(x)); return y;
}
// sigmoid with the 0.5 input scale PRE-FOLDED into weights/biases:
// caller passes a = 0.5*(gi+gh); sigmoid = 0.5*tanh(a) + 0.5
__device__ __forceinline__ float sig_from_half(float a) {
    return fmaf(0.5f, tanh_mufu(a), 0.5f);
}

// ---------------------------------------------------------------------------
// Kernel 1: transpose x [B, T] -> g_xT [T, B]
// ---------------------------------------------------------------------------
__global__ void transpose_kernel(const float* __restrict__ x) {
    __shared__ float tile[32][33];
    int t0 = blockIdx.x * 32;
    int b0 = blockIdx.y * 32;
    int tx = threadIdx.x, ty = threadIdx.y;
#pragma unroll
    for (int i = 0; i < 4; i++) {
        tile[ty + i * 8][tx] = x[(size_t)(b0 + ty + i * 8) * TT + (t0 + tx)];
    }
    __syncthreads();
#pragma unroll
    for (int i = 0; i < 4; i++) {
        g_xT[(size_t)(t0 + ty + i * 8) * BB + (b0 + tx)] = tile[tx][ty + i * 8];
    }
}

// ---------------------------------------------------------------------------
// Kernel 2: GRU scan — round-6 structure EXACTLY, with the n-gate weights
//           moved to SMEM so the r/z weights + hx fit in registers (no spill).
//   - 16-lane group handles one packed batch pair (f32x2 over 2 elements).
//   - Lane j owns hidden index j and gate rows {j, 16+j, 32+j}.
//     wr/wz: 32 ull in registers (batch-duplicated).
//     wn:    per-j row in SMEM, 16 duplicated ull, row stride 18 ull
//            (144 B: 16-byte aligned rows; bank offset 4 words/row -> the 16
//            distinct LDS.128 addresses tile the banks in the minimal 2
//            crossbar phases, conflict-free).
//   - Per-step h exchange via double-buffered SMEM (slots padded to 20 ull).
//   - __launch_bounds__(128,4): cap 128 regs ~= true need (~126) -> no spill.
//   - r/z weights+biases pre-scaled by 0.5 (sigmoid via tanh identity).
// ---------------------------------------------------------------------------

#define QPAD 20     // ull per pair slot in hbuf
#define WNSTRIDE 18 // ull per wn row (16 + 2 pad, 16B-aligned rows)

__global__ __launch_bounds__(128, 4)
void gru_kernel(const float* __restrict__ w_ih, const float* __restrict__ w_hh,
                const float* __restrict__ b_ih, const float* __restrict__ b_hh,
                const float* __restrict__ w_fc, const float* __restrict__ b_fc,
                float* __restrict__ out)
{
    __shared__ __align__(16) ull hbuf[2][8][QPAD];
    __shared__ __align__(16) ull wn_s[16 * WNSTRIDE];

    int tid = threadIdx.x;
    int g   = blockIdx.x * 128 + tid;
    int j   = g & 15;          // owned hidden index
    int p   = g >> 4;          // global batch-pair index (elements 2p, 2p+1)
    int pb  = tid >> 4;        // pair slot within block (0..7)

    // --- fill wn SMEM table (n-gate rows, batch-duplicated) ---
    for (int idx = tid; idx < 256; idx += 128) {
        int row = idx >> 4;
        int k   = idx & 15;
        float v = __ldg(&w_hh[(32 + row) * 16 + k]);
        wn_s[row * WNSTRIDE + k] = pk2(v, v);
    }

    // --- register-resident r/z weights (duplicated f32x2): 32 ull ---
    ull wr_[16], wz_[16];
#pragma unroll
    for (int k = 0; k < 16; k++) {
        float a = 0.5f * __ldg(&w_hh[j * 16 + k]);          // r row, half-scaled
        float b = 0.5f * __ldg(&w_hh[(16 + j) * 16 + k]);   // z row, half-scaled
        wr_[k] = pk2(a, a);
        wz_[k] = pk2(b, b);
    }

    // --- gate-input constants ---
    float wirf = 0.5f * __ldg(&w_ih[j]);
    float wizf = 0.5f * __ldg(&w_ih[16 + j]);
    float winf = __ldg(&w_ih[32 + j]);
    float bsrf = 0.5f * (__ldg(&b_ih[j]) + __ldg(&b_hh[j]));
    float bszf = 0.5f * (__ldg(&b_ih[16 + j]) + __ldg(&b_hh[16 + j]));
    float binf = __ldg(&b_ih[32 + j]);
    float bhnf = __ldg(&b_hh[32 + j]);
    ull wirp = pk2(wirf, wirf), wizp = pk2(wizf, wizf), winp = pk2(winf, winf);
    ull bsrp = pk2(bsrf, bsrf), bszp = pk2(bszf, bszf);
    ull binp = pk2(binf, binf), bhnp = pk2(bhnf, bhnf);

    const ull* wnrow = &wn_s[j * WNSTRIDE];

    // hx[k] = packed h_k for both elements; hown = own h_j
    ull hx[16];
#pragma unroll
    for (int k = 0; k < 16; k++) hx[k] = 0ull;
    ull hown = 0ull;

    __syncthreads();   // wn table visible

    const float2* xp = ((const float2*)g_xT) + p;
    float2 xv = __ldg(xp);
    xp += (BB / 2);

    int buf = 0;
    for (int t = 0; t < TT; t++) {
        ull x2 = pk2(xv.x, xv.y);
        float2 xnext = __ldg(xp);      // padded array: always valid
        xp += (BB / 2);

        // three gate pre-activations (independent FMA chains);
        // wn streamed from SMEM (8 LDS.128, conflict-free, phase-broadcast)
        ull aR = ffma2(x2, wirp, bsrp);
        ull aZ = ffma2(x2, wizp, bszp);
        ull aN = bhnp;
#pragma unroll
        for (int k2 = 0; k2 < 8; k2++) {
            ulonglong2 wnv = *(const ulonglong2*)(wnrow + 2 * k2);
            aR = ffma2(wr_[2 * k2], hx[2 * k2], aR);
            aZ = ffma2(wz_[2 * k2], hx[2 * k2], aZ);
            aN = ffma2(wnv.x,       hx[2 * k2], aN);
            aR = ffma2(wr_[2 * k2 + 1], hx[2 * k2 + 1], aR);
            aZ = ffma2(wz_[2 * k2 + 1], hx[2 * k2 + 1], aZ);
            aN = ffma2(wnv.y,           hx[2 * k2 + 1], aN);
        }

        float a0, a1;
        upk2(aR, a0, a1);
        ull rr = pk2(sig_from_half(a0), sig_from_half(a1));
        float z0, z1;
        upk2(aZ, z0, z1);
        z0 = sig_from_half(z0);
        z1 = sig_from_half(z1);

        ull gi  = ffma2(x2, winp, binp);
        ull pre = ffma2(rr, aN, gi);
        float p0, p1;
        upk2(pre, p0, p1);
        float n0 = tanh_mufu(p0);
        float n1 = tanh_mufu(p1);

        float h0, h1;
        upk2(hown, h0, h1);
        h0 = fmaf(z0, h0 - n0, n0);    // (1-z)n + z h
        h1 = fmaf(z1, h1 - n1, n1);
        hown = pk2(h0, h1);

        // exchange: write own h, sync, reload all 16
        hbuf[buf][pb][j] = hown;
        __syncwarp();
#pragma unroll
        for (int k2 = 0; k2 < 8; k2++) {
            ulonglong2 v = *(const ulonglong2*)&hbuf[buf][pb][2 * k2];
            hx[2 * k2]     = v.x;
            hx[2 * k2 + 1] = v.y;
        }
        buf ^= 1;

        xv = xnext;
    }

    // FC epilogue: out[b] = sum_j h[b][j] * w_fc[j] + b_fc
    float wf = __ldg(&w_fc[j]);
    float h0, h1;
    upk2(hown, h0, h1);
    float s0 = h0 * wf;
    float s1 = h1 * wf;
#pragma unroll
    for (int d = 1; d < 16; d <<= 1) {
        s0 += __shfl_xor_sync(0xffffffffu, s0, d);
        s1 += __shfl_xor_sync(0xffffffffu, s1, d);
    }
    if (j == 0) {
        float bf = __ldg(b_fc);
        float2 o;
        o.x = s0 + bf;
        o.y = s1 + bf;
        *(float2*)(out + 2 * p) = o;
    }
}

// ---------------------------------------------------------------------------
extern "C" void kernel_launch(void* const* d_in, const int* in_sizes, int n_in,
                              void* d_out, int out_size)
{
    const float* x    = (const float*)d_in[0];
    const float* w_ih = (const float*)d_in[1];
    const float* w_hh = (const float*)d_in[2];
    const float* b_ih = (const float*)d_in[3];
    const float* b_hh = (const float*)d_in[4];
    const float* w_fc = (const float*)d_in[5];
    const float* b_fc = (const float*)d_in[6];
    float* out = (float*)d_out;

    dim3 tb(32, 8);
    dim3 tg(TT / 32, BB / 32);
    transpose_kernel<<<tg, tb>>>(x);

    // 16384 batch / 2 per 16-lane group * 16 lanes = 131072 threads
    // = 1024 blocks x 128 threads (round-6 shape, spill-free weights).
    gru_kernel<<<1024, 128>>>(w_ih, w_hh, b_ih, b_hh, w_fc, b_fc, out);
}

// round 17
// speedup vs baseline: 1.3086x; 1.1996x over previous
#include <cuda_runtime.h>
#include <cstdint>

#define BB 16384
#define TT 2048

// Scratch: x transposed to [T, B]; padded by one timestep so the prefetch of
// t+1 never branches (last prefetched value is read but never used).
__device__ float g_xT[(size_t)BB * (size_t)(TT + 1)];

typedef unsigned long long ull;

__device__ __forceinline__ ull pk2(float a, float b) {
    ull r; asm("mov.b64 %0, {%1, %2};" : "=l"(r) : "f"(a), "f"(b)); return r;
}
__device__ __forceinline__ void upk2(ull v, float& a, float& b) {
    asm("mov.b64 {%0, %1}, %2;" : "=f"(a), "=f"(b) : "l"(v));
}
__device__ __forceinline__ ull ffma2(ull a, ull b, ull c) {
    ull d; asm("fma.rn.f32x2 %0, %1, %2, %3;" : "=l"(d) : "l"(a), "l"(b), "l"(c)); return d;
}
// MUFU.TANH — single-instruction tanh (sm_75+)
__device__ __forceinline__ float tanh_mufu(float x) {
    float y; asm("tanh.approx.f32 %0, %1;" : "=f"(y) : "f"(x)); return y;
}
// sigmoid with the 0.5 input scale PRE-FOLDED into weights/biases:
// caller passes a = 0.5*(gi+gh); sigmoid = 0.5*tanh(a) + 0.5
__device__ __forceinline__ float sig_from_half(float a) {
    return fmaf(0.5f, tanh_mufu(a), 0.5f);
}

// ---------------------------------------------------------------------------
// Kernel 1: transpose x [B, T] -> g_xT [T, B]
// ---------------------------------------------------------------------------
__global__ void transpose_kernel(const float* __restrict__ x) {
    __shared__ float tile[32][33];
    int t0 = blockIdx.x * 32;
    int b0 = blockIdx.y * 32;
    int tx = threadIdx.x, ty = threadIdx.y;
#pragma unroll
    for (int i = 0; i < 4; i++) {
        tile[ty + i * 8][tx] = x[(size_t)(b0 + ty + i * 8) * TT + (t0 + tx)];
    }
    __syncthreads();
#pragma unroll
    for (int i = 0; i < 4; i++) {
        g_xT[(size_t)(t0 + ty + i * 8) * BB + (b0 + tx)] = tile[tx][ty + i * 8];
    }
}

// ---------------------------------------------------------------------------
// Kernel 2: GRU scan — round-6 champion structure, with the register budget
//           it actually needs: __launch_bounds__(128, 3) -> 170-reg cap ->
//           all 48 weight ull + hx[16] TRULY register-resident, ZERO spills.
//   - 16-lane group handles one packed batch pair (f32x2 over 2 elements).
//   - Lane j owns hidden index j and gate rows {j, 16+j, 32+j}; 48 f32x2
//     duplicated weights in registers (96 regs) + hx 32 regs + ~20 live.
//   - Per-step h exchange via double-buffered SMEM with STATIC swapped
//     pointers (no per-step buffer-index ALU).
//   - 12 warps/SM (3/SMSP): issue math 2.33 gens x ~100 instr = 233 units
//     vs round-6's 1.75 x 143 = 250, with the spill LSU traffic gone.
//   - r/z weights+biases pre-scaled by 0.5 (sigmoid via tanh identity).
// ---------------------------------------------------------------------------

#define QPAD 20   // ull per pair slot (16 + 4 pad -> 8-bank offset between slots)

__global__ __launch_bounds__(128, 3)
void gru_kernel(const float* __restrict__ w_ih, const float* __restrict__ w_hh,
                const float* __restrict__ b_ih, const float* __restrict__ b_hh,
                const float* __restrict__ w_fc, const float* __restrict__ b_fc,
                float* __restrict__ out)
{
    __shared__ __align__(16) ull hbuf[2][8][QPAD];

    int tid = threadIdx.x;
    int g   = blockIdx.x * 128 + tid;
    int j   = g & 15;          // owned hidden index
    int p   = g >> 4;          // global batch-pair index (elements 2p, 2p+1)
    int pb  = tid >> 4;        // pair slot within block (0..7)

    // --- register-resident recurrent weights (duplicated f32x2): 48 ull ---
    ull wr_[16], wz_[16], wn_[16];
#pragma unroll
    for (int k = 0; k < 16; k++) {
        float a = 0.5f * __ldg(&w_hh[j * 16 + k]);          // r row, half-scaled
        float b = 0.5f * __ldg(&w_hh[(16 + j) * 16 + k]);   // z row, half-scaled
        float c = __ldg(&w_hh[(32 + j) * 16 + k]);          // n row
        wr_[k] = pk2(a, a);
        wz_[k] = pk2(b, b);
        wn_[k] = pk2(c, c);
    }

    // --- gate-input constants ---
    float wirf = 0.5f * __ldg(&w_ih[j]);
    float wizf = 0.5f * __ldg(&w_ih[16 + j]);
    float winf = __ldg(&w_ih[32 + j]);
    float bsrf = 0.5f * (__ldg(&b_ih[j]) + __ldg(&b_hh[j]));
    float bszf = 0.5f * (__ldg(&b_ih[16 + j]) + __ldg(&b_hh[16 + j]));
    float binf = __ldg(&b_ih[32 + j]);
    float bhnf = __ldg(&b_hh[32 + j]);
    ull wirp = pk2(wirf, wirf), wizp = pk2(wizf, wizf), winp = pk2(winf, winf);
    ull bsrp = pk2(bsrf, bsrf), bszp = pk2(bszf, bszf);
    ull binp = pk2(binf, binf), bhnp = pk2(bhnf, bhnf);

    // hx[k] = packed h_k for both elements; hown = own h_j
    ull hx[16];
#pragma unroll
    for (int k = 0; k < 16; k++) hx[k] = 0ull;
    ull hown = 0ull;

    // static ping-pong pointers (no per-step buffer-index ALU)
    ull* wrp = &hbuf[0][pb][0];
    ull* rdp = &hbuf[1][pb][0];

    const float2* xp = ((const float2*)g_xT) + p;
    float2 xv = __ldg(xp);
    xp += (BB / 2);

    for (int t = 0; t < TT; t++) {
        ull x2 = pk2(xv.x, xv.y);
        float2 xnext = __ldg(xp);      // padded array: always valid
        xp += (BB / 2);

        // three gate pre-activations (independent pure-register FMA chains)
        ull aR = ffma2(x2, wirp, bsrp);
        ull aZ = ffma2(x2, wizp, bszp);
        ull aN = bhnp;
#pragma unroll
        for (int k = 0; k < 16; k++) {
            aR = ffma2(wr_[k], hx[k], aR);
            aZ = ffma2(wz_[k], hx[k], aZ);
            aN = ffma2(wn_[k], hx[k], aN);
        }

        float a0, a1;
        upk2(aR, a0, a1);
        ull rr = pk2(sig_from_half(a0), sig_from_half(a1));
        float z0, z1;
        upk2(aZ, z0, z1);
        z0 = sig_from_half(z0);
        z1 = sig_from_half(z1);

        ull gi  = ffma2(x2, winp, binp);
        ull pre = ffma2(rr, aN, gi);
        float p0, p1;
        upk2(pre, p0, p1);
        float n0 = tanh_mufu(p0);
        float n1 = tanh_mufu(p1);

        float h0, h1;
        upk2(hown, h0, h1);
        h0 = fmaf(z0, h0 - n0, n0);    // (1-z)n + z h
        h1 = fmaf(z1, h1 - n1, n1);
        hown = pk2(h0, h1);

        // exchange: write own h, sync, reload all 16
        wrp[j] = hown;
        __syncwarp();
#pragma unroll
        for (int k2 = 0; k2 < 8; k2++) {
            ulonglong2 v = *(const ulonglong2*)(wrp + 2 * k2);
            hx[2 * k2]     = v.x;
            hx[2 * k2 + 1] = v.y;
        }
        ull* tmp = rdp; rdp = wrp; wrp = tmp;

        xv = xnext;
    }

    // FC epilogue: out[b] = sum_j h[b][j] * w_fc[j] + b_fc
    float wf = __ldg(&w_fc[j]);
    float h0, h1;
    upk2(hown, h0, h1);
    float s0 = h0 * wf;
    float s1 = h1 * wf;
#pragma unroll
    for (int d = 1; d < 16; d <<= 1) {
        s0 += __shfl_xor_sync(0xffffffffu, s0, d);
        s1 += __shfl_xor_sync(0xffffffffu, s1, d);
    }
    if (j == 0) {
        float bf = __ldg(b_fc);
        float2 o;
        o.x = s0 + bf;
        o.y = s1 + bf;
        *(float2*)(out + 2 * p) = o;
    }
}

// ---------------------------------------------------------------------------
extern "C" void kernel_launch(void* const* d_in, const int* in_sizes, int n_in,
                              void* d_out, int out_size)
{
    const float* x    = (const float*)d_in[0];
    const float* w_ih = (const float*)d_in[1];
    const float* w_hh = (const float*)d_in[2];
    const float* b_ih = (const float*)d_in[3];
    const float* b_hh = (const float*)d_in[4];
    const float* w_fc = (const float*)d_in[5];
    const float* b_fc = (const float*)d_in[6];
    float* out = (float*)d_out;

    dim3 tb(32, 8);
    dim3 tg(TT / 32, BB / 32);
    transpose_kernel<<<tg, tb>>>(x);

    // 16384 batch / 2 per 16-lane group * 16 lanes = 131072 threads
    // = 1024 blocks x 128 threads; (128,3) -> 170-reg cap, no spills.
    gru_kernel<<<1024, 128>>>(w_ih, w_hh, b_ih, b_hh, w_fc, b_fc, out);
}